// round 2
// baseline (speedup 1.0000x reference)
#include <cuda_runtime.h>
#include <float.h>

#define HID   256
#define NH1   8
#define MAXN  20992
#define MAXE0 102400
#define MAXT  (MAXE0 + MAXN)

// ---------------- static device scratch (no allocations allowed) ----------------
static __device__ float g_x0 [(size_t)MAXN * HID];
static __device__ float g_h1 [(size_t)MAXN * NH1 * HID];
static __device__ float g_o1 [(size_t)MAXN * NH1 * HID];
static __device__ float g_h2 [(size_t)MAXN * HID];
static __device__ float g_o2 [(size_t)MAXN * HID];
static __device__ float g_as1[MAXN * NH1];
static __device__ float g_ad1[MAXN * NH1];
static __device__ float g_m1 [MAXN * NH1];
static __device__ float g_dn1[MAXN * NH1];
static __device__ float g_as2[MAXN];
static __device__ float g_ad2[MAXN];
static __device__ float g_m2 [MAXN];
static __device__ float g_dn2[MAXN];
static __device__ float g_e1 [(size_t)MAXT * NH1];
static __device__ float g_e2 [MAXT];
static __device__ float g_wnf[HID * 64];
static __device__ float g_wcf[HID * 128];
static __device__ int   g_eidx[2 * MAXE0];
static __device__ int   g_is64;

// ---------------- edge dtype detection + normalization ----------------
// Reference writes jnp.int64, but JAX without x64 silently produces int32.
// Detect on device: int32 pairs reinterpreted as int64 are astronomically large.
__global__ void detect_edges_kernel(const void* p, int E0, int N) {
    if (blockIdx.x != 0 || threadIdx.x != 0) return;
    const long long* q = (const long long*)p;
    int scan = 2 * E0 < 512 ? 2 * E0 : 512;
    int ok = 1;
    for (int i = 0; i < scan; i++) {
        long long v = q[i];
        if (v < 0 || v >= (long long)N) { ok = 0; break; }
    }
    g_is64 = ok;
}

__global__ void convert_edges_kernel(const void* p, int n) {  // n = 2*E0
    int i = blockIdx.x * blockDim.x + threadIdx.x;
    if (i >= n) return;
    if (g_is64) g_eidx[i] = (int)((const long long*)p)[i];
    else        g_eidx[i] = ((const int*)p)[i];
}

// ---------------- weight folding for tile(x, (1,2)) ----------------
__global__ void fold_w_kernel(const float* __restrict__ Wn, const float* __restrict__ Wc) {
    int i = blockIdx.x * blockDim.x + threadIdx.x;
    if (i < HID * 64) {
        int j = i >> 6, k = i & 63;
        g_wnf[i] = Wn[j * 128 + k] + Wn[j * 128 + 64 + k];
    }
    if (i < HID * 128) {
        int j = i >> 7, k = i & 127;
        g_wcf[i] = Wc[j * 256 + k] + Wc[j * 256 + 128 + k];
    }
}

// ---------------- fp32 tiled GEMM:  C[M,N] = A[M,K] * B[N,K]^T (+bias)(+relu) ----
// 128x128 block, BK=16, 256 threads, 8x8 register microtile per thread.
__global__ __launch_bounds__(256) void gemm_tn_kernel(
    const float* __restrict__ A, const float* __restrict__ B, float* __restrict__ C,
    int M, int N, int K, const float* __restrict__ bias, int relu)
{
    __shared__ float As[16][128];
    __shared__ float Bs[16][128];

    int tid = threadIdx.x;
    int tx = tid & 15, ty = tid >> 4;
    int row0 = blockIdx.y * 128;
    int col0 = blockIdx.x * 128;

    float acc[8][8];
#pragma unroll
    for (int i = 0; i < 8; i++)
#pragma unroll
        for (int j = 0; j < 8; j++) acc[i][j] = 0.f;

    for (int k0 = 0; k0 < K; k0 += 16) {
#pragma unroll
        for (int t = 0; t < 2; t++) {
            int idx = tid + t * 256;          // 0..511 float4 slots
            int r   = idx >> 2;
            int kk  = (idx & 3) * 4;
            int gr  = row0 + r;
            float4 v = make_float4(0.f, 0.f, 0.f, 0.f);
            if (gr < M) v = *(const float4*)(A + (size_t)gr * K + k0 + kk);
            As[kk + 0][r] = v.x; As[kk + 1][r] = v.y;
            As[kk + 2][r] = v.z; As[kk + 3][r] = v.w;
        }
#pragma unroll
        for (int t = 0; t < 2; t++) {
            int idx = tid + t * 256;
            int r   = idx >> 2;
            int kk  = (idx & 3) * 4;
            int gc  = col0 + r;
            float4 v = make_float4(0.f, 0.f, 0.f, 0.f);
            if (gc < N) v = *(const float4*)(B + (size_t)gc * K + k0 + kk);
            Bs[kk + 0][r] = v.x; Bs[kk + 1][r] = v.y;
            Bs[kk + 2][r] = v.z; Bs[kk + 3][r] = v.w;
        }
        __syncthreads();

#pragma unroll
        for (int kk = 0; kk < 16; kk++) {
            float a[8], b[8];
            *(float4*)(a)     = *(float4*)&As[kk][ty * 8];
            *(float4*)(a + 4) = *(float4*)&As[kk][ty * 8 + 4];
            *(float4*)(b)     = *(float4*)&Bs[kk][tx * 8];
            *(float4*)(b + 4) = *(float4*)&Bs[kk][tx * 8 + 4];
#pragma unroll
            for (int i = 0; i < 8; i++)
#pragma unroll
                for (int j = 0; j < 8; j++) acc[i][j] += a[i] * b[j];
        }
        __syncthreads();
    }

    float bv[8];
#pragma unroll
    for (int j = 0; j < 8; j++) {
        int c = col0 + tx * 8 + j;
        bv[j] = (bias && c < N) ? bias[c] : 0.f;
    }

#pragma unroll
    for (int i = 0; i < 8; i++) {
        int r = row0 + ty * 8 + i;
        if (r >= M) continue;
        int c = col0 + tx * 8;
        if (c + 7 >= N) continue;   // N is always a multiple of 128 in our calls
        float o[8];
#pragma unroll
        for (int j = 0; j < 8; j++) {
            float v = acc[i][j] + bv[j];
            if (relu) v = v > 0.f ? v : 0.f;
            o[j] = v;
        }
        float* cp = C + (size_t)r * N + c;
        *(float4*)(cp)     = make_float4(o[0], o[1], o[2], o[3]);
        *(float4*)(cp + 4) = make_float4(o[4], o[5], o[6], o[7]);
    }
}

// ---------------- attention coefficients: warp per (node, head) ----------------
__global__ void att_coef_kernel(const float* __restrict__ h,
                                const float* __restrict__ avs, const float* __restrict__ avd,
                                float* __restrict__ os, float* __restrict__ od, int H)
{
    int n = blockIdx.x;
    int w = threadIdx.x >> 5;
    int lane = threadIdx.x & 31;
    const float* hp = h + ((size_t)n * H + w) * HID;
    float s = 0.f, d = 0.f;
    for (int c = lane; c < HID; c += 32) {
        float v = hp[c];
        s += v * avs[w * HID + c];
        d += v * avd[w * HID + c];
    }
#pragma unroll
    for (int o = 16; o; o >>= 1) {
        s += __shfl_down_sync(0xffffffffu, s, o);
        d += __shfl_down_sync(0xffffffffu, d, o);
    }
    if (lane == 0) { os[n * H + w] = s; od[n * H + w] = d; }
}

__global__ void init_softmax_kernel(float* __restrict__ m, float* __restrict__ dn, int n) {
    int i = blockIdx.x * blockDim.x + threadIdx.x;
    if (i < n) { m[i] = -FLT_MAX; dn[i] = 0.f; }
}

__device__ __forceinline__ void atomicMaxF(float* addr, float v) {
    int old = __float_as_int(*addr);
    while (__int_as_float(old) < v) {
        int assumed = old;
        old = atomicCAS((int*)addr, assumed, __float_as_int(v));
        if (old == assumed) break;
    }
}

// leaky_relu(a_s[src]+a_d[dst]) -> store logit, atomic segment max over dst
__global__ void edge_logit_max_kernel(const float* __restrict__ as_, const float* __restrict__ ad_,
                                      const int* __restrict__ esrc, const int* __restrict__ edst,
                                      int E0, int N, int H,
                                      float* __restrict__ ebuf, float* __restrict__ m)
{
    int idx = blockIdx.x * blockDim.x + threadIdx.x;
    int total = (E0 + N) * H;
    if (idx >= total) return;
    int i = idx / H, hh = idx - i * H;
    int src, dst;
    if (i < E0) { src = esrc[i]; dst = edst[i]; }
    else        { src = dst = i - E0; }
    float e = as_[src * H + hh] + ad_[dst * H + hh];
    e = e > 0.f ? e : 0.2f * e;
    ebuf[idx] = e;
    atomicMaxF(&m[dst * H + hh], e);
}

// exp(e - m[dst]) -> store, atomic segment sum over dst
__global__ void edge_exp_kernel(const int* __restrict__ edst, int E0, int N, int H,
                                float* __restrict__ ebuf,
                                const float* __restrict__ m, float* __restrict__ dn)
{
    int idx = blockIdx.x * blockDim.x + threadIdx.x;
    int total = (E0 + N) * H;
    if (idx >= total) return;
    int i = idx / H, hh = idx - i * H;
    int dst = (i < E0) ? edst[i] : (i - E0);
    float v = expf(ebuf[idx] - m[dst * H + hh]);
    ebuf[idx] = v;
    atomicAdd(&dn[dst * H + hh], v);
}

// warp per (edge, head): out[dst,h,:] += alpha * hsrc[src,h,:]   (C = HID = 256)
__global__ void edge_aggregate_kernel(const float* __restrict__ h, const float* __restrict__ ebuf,
                                      const float* __restrict__ dn,
                                      const int* __restrict__ esrc, const int* __restrict__ edst,
                                      int E0, int N, int H, float* __restrict__ out)
{
    int w    = (blockIdx.x * blockDim.x + threadIdx.x) >> 5;
    int lane = threadIdx.x & 31;
    int total = (E0 + N) * H;
    if (w >= total) return;
    int i = w / H, hh = w - i * H;
    int src, dst;
    if (i < E0) { src = esrc[i]; dst = edst[i]; }
    else        { src = dst = i - E0; }
    float alpha = ebuf[w] / (dn[dst * H + hh] + 1e-16f);
    const float4* hp = (const float4*)(h + ((size_t)src * H + hh) * HID);
    float*        op = out + ((size_t)dst * H + hh) * HID;
    float4 v = hp[lane];
    atomicAdd(op + lane * 4 + 0, alpha * v.x);
    atomicAdd(op + lane * 4 + 1, alpha * v.y);
    atomicAdd(op + lane * 4 + 2, alpha * v.z);
    atomicAdd(op + lane * 4 + 3, alpha * v.w);
    v = hp[lane + 32];
    atomicAdd(op + (lane + 32) * 4 + 0, alpha * v.x);
    atomicAdd(op + (lane + 32) * 4 + 1, alpha * v.y);
    atomicAdd(op + (lane + 32) * 4 + 2, alpha * v.z);
    atomicAdd(op + (lane + 32) * 4 + 3, alpha * v.w);
}

// x = relu(x + bias), vectorized float4.  n4 = total_elems/4, C = row width (mult of 4)
__global__ void bias_relu_kernel(float* __restrict__ x, const float* __restrict__ b, int n4, int C) {
    int i = blockIdx.x * blockDim.x + threadIdx.x;
    if (i >= n4) return;
    int c = (i * 4) % C;
    float4 v = ((float4*)x)[i];
    v.x += b[c + 0]; v.y += b[c + 1]; v.z += b[c + 2]; v.w += b[c + 3];
    v.x = v.x > 0.f ? v.x : 0.f;
    v.y = v.y > 0.f ? v.y : 0.f;
    v.z = v.z > 0.f ? v.z : 0.f;
    v.w = v.w > 0.f ? v.w : 0.f;
    ((float4*)x)[i] = v;
}

// ---------------- launch ----------------
extern "C" void kernel_launch(void* const* d_in, const int* in_sizes, int n_in,
                              void* d_out, int out_size)
{
    const float* cs    = (const float*)d_in[0];
    const float* cols  = (const float*)d_in[1];
    const void*  edges = d_in[2];
    const float* W_node = (const float*)d_in[3];
    const float* b_node = (const float*)d_in[4];
    const float* W_col  = (const float*)d_in[5];
    const float* b_col  = (const float*)d_in[6];
    const float* W1     = (const float*)d_in[7];
    const float* attS1  = (const float*)d_in[8];
    const float* attD1  = (const float*)d_in[9];
    const float* b1     = (const float*)d_in[10];
    const float* W2     = (const float*)d_in[11];
    const float* attS2  = (const float*)d_in[12];
    const float* attD2  = (const float*)d_in[13];
    const float* b2     = (const float*)d_in[14];
    const float* W_out  = (const float*)d_in[15];
    const float* b_out  = (const float*)d_in[16];
    float* out = (float*)d_out;

    int Nc   = in_sizes[0] / 64;
    int Ncol = in_sizes[1] / 128;
    int E0   = in_sizes[2] / 2;
    int N    = Nc + Ncol;

    float *x0, *h1, *o1, *h2, *o2;
    float *pas1, *pad1, *pm1, *pdn1, *pas2, *pad2, *pm2, *pdn2, *e1, *e2, *wnf, *wcf;
    int *eidx;
    cudaGetSymbolAddress((void**)&x0,  g_x0);
    cudaGetSymbolAddress((void**)&h1,  g_h1);
    cudaGetSymbolAddress((void**)&o1,  g_o1);
    cudaGetSymbolAddress((void**)&h2,  g_h2);
    cudaGetSymbolAddress((void**)&o2,  g_o2);
    cudaGetSymbolAddress((void**)&pas1, g_as1);
    cudaGetSymbolAddress((void**)&pad1, g_ad1);
    cudaGetSymbolAddress((void**)&pm1,  g_m1);
    cudaGetSymbolAddress((void**)&pdn1, g_dn1);
    cudaGetSymbolAddress((void**)&pas2, g_as2);
    cudaGetSymbolAddress((void**)&pad2, g_ad2);
    cudaGetSymbolAddress((void**)&pm2,  g_m2);
    cudaGetSymbolAddress((void**)&pdn2, g_dn2);
    cudaGetSymbolAddress((void**)&e1,  g_e1);
    cudaGetSymbolAddress((void**)&e2,  g_e2);
    cudaGetSymbolAddress((void**)&wnf, g_wnf);
    cudaGetSymbolAddress((void**)&wcf, g_wcf);
    cudaGetSymbolAddress((void**)&eidx, g_eidx);

    // --- edge normalization ---
    detect_edges_kernel<<<1, 32>>>(edges, E0, N);
    convert_edges_kernel<<<(2 * E0 + 255) / 256, 256>>>(edges, 2 * E0);
    const int* er0 = eidx;        // edges[0]
    const int* er1 = eidx + E0;   // edges[1]

    // --- encoder (tile fold + GEMM + bias + relu) ---
    fold_w_kernel<<<(HID * 128 + 255) / 256, 256>>>(W_node, W_col);
    gemm_tn_kernel<<<dim3(HID / 128, (Nc + 127) / 128), 256>>>(cs, wnf, x0, Nc, HID, 64, b_node, 1);
    gemm_tn_kernel<<<dim3(HID / 128, (Ncol + 127) / 128), 256>>>(cols, wcf, x0 + (size_t)Nc * HID, Ncol, HID, 128, b_col, 1);

    // --- conv1 (8 heads) ---
    gemm_tn_kernel<<<dim3(NH1 * HID / 128, (N + 127) / 128), 256>>>(x0, W1, h1, N, NH1 * HID, HID, nullptr, 0);
    att_coef_kernel<<<N, 32 * NH1>>>(h1, attS1, attD1, pas1, pad1, NH1);
    init_softmax_kernel<<<(N * NH1 + 255) / 256, 256>>>(pm1, pdn1, N * NH1);
    cudaMemsetAsync(o1, 0, (size_t)N * NH1 * HID * sizeof(float), 0);
    int tot1 = (E0 + N) * NH1;
    edge_logit_max_kernel<<<(tot1 + 255) / 256, 256>>>(pas1, pad1, er0, er1, E0, N, NH1, e1, pm1);
    edge_exp_kernel<<<(tot1 + 255) / 256, 256>>>(er1, E0, N, NH1, e1, pm1, pdn1);
    {
        long long threads = (long long)tot1 * 32;
        edge_aggregate_kernel<<<(unsigned)((threads + 255) / 256), 256>>>(h1, e1, pdn1, er0, er1, E0, N, NH1, o1);
    }
    bias_relu_kernel<<<((N * NH1 * HID / 4) + 255) / 256, 256>>>(o1, b1, N * NH1 * HID / 4, NH1 * HID);

    // --- conv2 (1 head, flipped edges) ---
    gemm_tn_kernel<<<dim3(HID / 128, (N + 127) / 128), 256>>>(o1, W2, h2, N, HID, NH1 * HID, nullptr, 0);
    att_coef_kernel<<<N, 32>>>(h2, attS2, attD2, pas2, pad2, 1);
    init_softmax_kernel<<<(N + 255) / 256, 256>>>(pm2, pdn2, N);
    cudaMemsetAsync(o2, 0, (size_t)N * HID * sizeof(float), 0);
    int tot2 = E0 + N;
    edge_logit_max_kernel<<<(tot2 + 255) / 256, 256>>>(pas2, pad2, er1, er0, E0, N, 1, e2, pm2);
    edge_exp_kernel<<<(tot2 + 255) / 256, 256>>>(er0, E0, N, 1, e2, pm2, pdn2);
    {
        long long threads = (long long)tot2 * 32;
        edge_aggregate_kernel<<<(unsigned)((threads + 255) / 256), 256>>>(h2, e2, pdn2, er1, er0, E0, N, 1, o2);
    }
    bias_relu_kernel<<<((N * HID / 4) + 255) / 256, 256>>>(o2, b2, N * HID / 4, HID);

    // --- output projection (column nodes only) ---
    gemm_tn_kernel<<<dim3(128 / 128, (Ncol + 127) / 128), 256>>>(o2 + (size_t)Nc * HID, W_out, out, Ncol, 128, HID, b_out, 0);
}

// round 3
// speedup vs baseline: 1.2290x; 1.2290x over previous
#include <cuda_runtime.h>
#include <float.h>
#include <stdint.h>

#define HID   256
#define NH1   8
#define MAXN  20992
#define MAXE0 102400
#define MAXT  (MAXE0 + MAXN)

// ---------------- static device scratch (no allocations allowed) ----------------
static __device__ float g_x0 [(size_t)MAXN * HID];
static __device__ float g_h1 [(size_t)MAXN * NH1 * HID];
static __device__ float g_o1 [(size_t)MAXN * NH1 * HID];
static __device__ float g_h2 [(size_t)MAXN * HID];
static __device__ float g_o2 [(size_t)MAXN * HID];
static __device__ float g_as1[MAXN * NH1];
static __device__ float g_ad1[MAXN * NH1];
static __device__ float g_m1 [MAXN * NH1];
static __device__ float g_dn1[MAXN * NH1];
static __device__ float g_as2[MAXN];
static __device__ float g_ad2[MAXN];
static __device__ float g_m2 [MAXN];
static __device__ float g_dn2[MAXN];
static __device__ float g_e1 [(size_t)MAXT * NH1];
static __device__ float g_e2 [MAXT];
static __device__ float g_wnf[HID * 64];
static __device__ float g_wcf[HID * 128];
static __device__ int   g_eidx[2 * MAXE0];
static __device__ int   g_is64;

// ---------------- edge dtype detection + normalization ----------------
__global__ void detect_edges_kernel(const void* p, int E0, int N) {
    if (blockIdx.x != 0 || threadIdx.x != 0) return;
    const long long* q = (const long long*)p;
    int scan = 2 * E0 < 512 ? 2 * E0 : 512;
    int ok = 1;
    for (int i = 0; i < scan; i++) {
        long long v = q[i];
        if (v < 0 || v >= (long long)N) { ok = 0; break; }
    }
    g_is64 = ok;
}

__global__ void convert_edges_kernel(const void* p, int n) {
    int i = blockIdx.x * blockDim.x + threadIdx.x;
    if (i >= n) return;
    if (g_is64) g_eidx[i] = (int)((const long long*)p)[i];
    else        g_eidx[i] = ((const int*)p)[i];
}

// ---------------- weight folding for tile(x, (1,2)) ----------------
__global__ void fold_w_kernel(const float* __restrict__ Wn, const float* __restrict__ Wc) {
    int i = blockIdx.x * blockDim.x + threadIdx.x;
    if (i < HID * 64) {
        int j = i >> 6, k = i & 63;
        g_wnf[i] = Wn[j * 128 + k] + Wn[j * 128 + 64 + k];
    }
    if (i < HID * 128) {
        int j = i >> 7, k = i & 127;
        g_wcf[i] = Wc[j * 256 + k] + Wc[j * 256 + 128 + k];
    }
}

// ---------------- TF32 tensor-core GEMM: C[M,N] = A[M,K]*B[N,K]^T (+bias)(+relu)
// 128x128 block tile, BK=32, 256 threads = 8 warps (2m x 4n), warp tile 64x32.
// mma.sync.m16n8k8 tf32, fp32 accumulate. Requires N%128==0, K%32==0.
// Smem stride 36 floats => conflict-free STS.128 fills and fragment LDS.
__device__ __forceinline__ float to_tf32(float x) {
    asm("cvt.rna.tf32.f32 %0, %0;" : "+f"(x));
    return x;
}

__device__ __forceinline__ void mma_tf32(float c[4],
                                         uint32_t a0, uint32_t a1, uint32_t a2, uint32_t a3,
                                         uint32_t b0, uint32_t b1) {
    asm volatile(
        "mma.sync.aligned.m16n8k8.row.col.f32.tf32.tf32.f32 "
        "{%0,%1,%2,%3}, {%4,%5,%6,%7}, {%8,%9}, {%0,%1,%2,%3};"
        : "+f"(c[0]), "+f"(c[1]), "+f"(c[2]), "+f"(c[3])
        : "r"(a0), "r"(a1), "r"(a2), "r"(a3), "r"(b0), "r"(b1));
}

#define SSTR 36

__global__ __launch_bounds__(256, 2) void gemm_tf32_kernel(
    const float* __restrict__ A, const float* __restrict__ B, float* __restrict__ C,
    int M, int N, int K, const float* __restrict__ bias, int relu)
{
    __shared__ float As[128 * SSTR];
    __shared__ float Bs[128 * SSTR];

    int tid  = threadIdx.x;
    int wid  = tid >> 5;
    int lane = tid & 31;
    int grp  = lane >> 2;       // 0..7
    int tig  = lane & 3;        // 0..3
    int wm   = wid & 1;         // m offset wm*64
    int wn   = wid >> 1;        // n offset wn*32
    int row0 = blockIdx.y * 128;
    int col0 = blockIdx.x * 128;

    // fill indices: each thread loads 4 float4 tiles per buffer
    int lrow = tid >> 3;        // 0..31 (base row, +32 per iteration)
    int lkq  = (tid & 7) * 4;   // k quad

    float c[4][4][4];
#pragma unroll
    for (int mi = 0; mi < 4; mi++)
#pragma unroll
        for (int ni = 0; ni < 4; ni++)
#pragma unroll
            for (int j = 0; j < 4; j++) c[mi][ni][j] = 0.f;

    for (int k0 = 0; k0 < K; k0 += 32) {
#pragma unroll
        for (int it = 0; it < 4; it++) {
            int r  = lrow + it * 32;
            int gr = row0 + r;
            float4 v = make_float4(0.f, 0.f, 0.f, 0.f);
            if (gr < M) v = *(const float4*)(A + (size_t)gr * K + k0 + lkq);
            float* s = As + r * SSTR + lkq;
            s[0] = to_tf32(v.x); s[1] = to_tf32(v.y);
            s[2] = to_tf32(v.z); s[3] = to_tf32(v.w);
        }
#pragma unroll
        for (int it = 0; it < 4; it++) {
            int r  = lrow + it * 32;
            float4 v = *(const float4*)(B + (size_t)(col0 + r) * K + k0 + lkq);
            float* s = Bs + r * SSTR + lkq;
            s[0] = to_tf32(v.x); s[1] = to_tf32(v.y);
            s[2] = to_tf32(v.z); s[3] = to_tf32(v.w);
        }
        __syncthreads();

#pragma unroll
        for (int ks = 0; ks < 4; ks++) {
            int kk = ks * 8;
            uint32_t af[4][4], bf[4][2];
#pragma unroll
            for (int mi = 0; mi < 4; mi++) {
                const float* ap = As + (wm * 64 + mi * 16 + grp) * SSTR + kk + tig;
                af[mi][0] = __float_as_uint(ap[0]);
                af[mi][1] = __float_as_uint(ap[8 * SSTR]);
                af[mi][2] = __float_as_uint(ap[4]);
                af[mi][3] = __float_as_uint(ap[8 * SSTR + 4]);
            }
#pragma unroll
            for (int ni = 0; ni < 4; ni++) {
                const float* bp = Bs + (wn * 32 + ni * 8 + grp) * SSTR + kk + tig;
                bf[ni][0] = __float_as_uint(bp[0]);
                bf[ni][1] = __float_as_uint(bp[4]);
            }
#pragma unroll
            for (int mi = 0; mi < 4; mi++)
#pragma unroll
                for (int ni = 0; ni < 4; ni++)
                    mma_tf32(c[mi][ni], af[mi][0], af[mi][1], af[mi][2], af[mi][3],
                             bf[ni][0], bf[ni][1]);
        }
        __syncthreads();
    }

    // epilogue: C rows grp / grp+8 per m-tile, cols 2*tig / 2*tig+1 per n-tile
#pragma unroll
    for (int mi = 0; mi < 4; mi++) {
#pragma unroll
        for (int half = 0; half < 2; half++) {
            int r = row0 + wm * 64 + mi * 16 + grp + half * 8;
            if (r >= M) continue;
#pragma unroll
            for (int ni = 0; ni < 4; ni++) {
                int cc = col0 + wn * 32 + ni * 8 + 2 * tig;
                float v0 = c[mi][ni][half * 2 + 0];
                float v1 = c[mi][ni][half * 2 + 1];
                if (bias) { v0 += bias[cc]; v1 += bias[cc + 1]; }
                if (relu) { v0 = v0 > 0.f ? v0 : 0.f; v1 = v1 > 0.f ? v1 : 0.f; }
                *(float2*)(C + (size_t)r * N + cc) = make_float2(v0, v1);
            }
        }
    }
}

// ---------------- attention coefficients: warp per (node, head) ----------------
__global__ void att_coef_kernel(const float* __restrict__ h,
                                const float* __restrict__ avs, const float* __restrict__ avd,
                                float* __restrict__ os, float* __restrict__ od, int H)
{
    int n = blockIdx.x;
    int w = threadIdx.x >> 5;
    int lane = threadIdx.x & 31;
    const float* hp = h + ((size_t)n * H + w) * HID;
    float s = 0.f, d = 0.f;
    for (int c = lane; c < HID; c += 32) {
        float v = hp[c];
        s += v * avs[w * HID + c];
        d += v * avd[w * HID + c];
    }
#pragma unroll
    for (int o = 16; o; o >>= 1) {
        s += __shfl_down_sync(0xffffffffu, s, o);
        d += __shfl_down_sync(0xffffffffu, d, o);
    }
    if (lane == 0) { os[n * H + w] = s; od[n * H + w] = d; }
}

__global__ void init_softmax_kernel(float* __restrict__ m, float* __restrict__ dn, int n) {
    int i = blockIdx.x * blockDim.x + threadIdx.x;
    if (i < n) { m[i] = -FLT_MAX; dn[i] = 0.f; }
}

__device__ __forceinline__ void atomicMaxF(float* addr, float v) {
    int old = __float_as_int(*addr);
    while (__int_as_float(old) < v) {
        int assumed = old;
        old = atomicCAS((int*)addr, assumed, __float_as_int(v));
        if (old == assumed) break;
    }
}

__global__ void edge_logit_max_kernel(const float* __restrict__ as_, const float* __restrict__ ad_,
                                      const int* __restrict__ esrc, const int* __restrict__ edst,
                                      int E0, int N, int H,
                                      float* __restrict__ ebuf, float* __restrict__ m)
{
    int idx = blockIdx.x * blockDim.x + threadIdx.x;
    int total = (E0 + N) * H;
    if (idx >= total) return;
    int i = idx / H, hh = idx - i * H;
    int src, dst;
    if (i < E0) { src = esrc[i]; dst = edst[i]; }
    else        { src = dst = i - E0; }
    float e = as_[src * H + hh] + ad_[dst * H + hh];
    e = e > 0.f ? e : 0.2f * e;
    ebuf[idx] = e;
    atomicMaxF(&m[dst * H + hh], e);
}

__global__ void edge_exp_kernel(const int* __restrict__ edst, int E0, int N, int H,
                                float* __restrict__ ebuf,
                                const float* __restrict__ m, float* __restrict__ dn)
{
    int idx = blockIdx.x * blockDim.x + threadIdx.x;
    int total = (E0 + N) * H;
    if (idx >= total) return;
    int i = idx / H, hh = idx - i * H;
    int dst = (i < E0) ? edst[i] : (i - E0);
    float v = expf(ebuf[idx] - m[dst * H + hh]);
    ebuf[idx] = v;
    atomicAdd(&dn[dst * H + hh], v);
}

__global__ void edge_aggregate_kernel(const float* __restrict__ h, const float* __restrict__ ebuf,
                                      const float* __restrict__ dn,
                                      const int* __restrict__ esrc, const int* __restrict__ edst,
                                      int E0, int N, int H, float* __restrict__ out)
{
    int w    = (blockIdx.x * blockDim.x + threadIdx.x) >> 5;
    int lane = threadIdx.x & 31;
    int total = (E0 + N) * H;
    if (w >= total) return;
    int i = w / H, hh = w - i * H;
    int src, dst;
    if (i < E0) { src = esrc[i]; dst = edst[i]; }
    else        { src = dst = i - E0; }
    float alpha = ebuf[w] / (dn[dst * H + hh] + 1e-16f);
    const float4* hp = (const float4*)(h + ((size_t)src * H + hh) * HID);
    float*        op = out + ((size_t)dst * H + hh) * HID;
    float4 v = hp[lane];
    atomicAdd(op + lane * 4 + 0, alpha * v.x);
    atomicAdd(op + lane * 4 + 1, alpha * v.y);
    atomicAdd(op + lane * 4 + 2, alpha * v.z);
    atomicAdd(op + lane * 4 + 3, alpha * v.w);
    v = hp[lane + 32];
    atomicAdd(op + (lane + 32) * 4 + 0, alpha * v.x);
    atomicAdd(op + (lane + 32) * 4 + 1, alpha * v.y);
    atomicAdd(op + (lane + 32) * 4 + 2, alpha * v.z);
    atomicAdd(op + (lane + 32) * 4 + 3, alpha * v.w);
}

__global__ void bias_relu_kernel(float* __restrict__ x, const float* __restrict__ b, int n4, int C) {
    int i = blockIdx.x * blockDim.x + threadIdx.x;
    if (i >= n4) return;
    int c = (i * 4) % C;
    float4 v = ((float4*)x)[i];
    v.x += b[c + 0]; v.y += b[c + 1]; v.z += b[c + 2]; v.w += b[c + 3];
    v.x = v.x > 0.f ? v.x : 0.f;
    v.y = v.y > 0.f ? v.y : 0.f;
    v.z = v.z > 0.f ? v.z : 0.f;
    v.w = v.w > 0.f ? v.w : 0.f;
    ((float4*)x)[i] = v;
}

// ---------------- launch ----------------
extern "C" void kernel_launch(void* const* d_in, const int* in_sizes, int n_in,
                              void* d_out, int out_size)
{
    const float* cs    = (const float*)d_in[0];
    const float* cols  = (const float*)d_in[1];
    const void*  edges = d_in[2];
    const float* W_node = (const float*)d_in[3];
    const float* b_node = (const float*)d_in[4];
    const float* W_col  = (const float*)d_in[5];
    const float* b_col  = (const float*)d_in[6];
    const float* W1     = (const float*)d_in[7];
    const float* attS1  = (const float*)d_in[8];
    const float* attD1  = (const float*)d_in[9];
    const float* b1     = (const float*)d_in[10];
    const float* W2     = (const float*)d_in[11];
    const float* attS2  = (const float*)d_in[12];
    const float* attD2  = (const float*)d_in[13];
    const float* b2     = (const float*)d_in[14];
    const float* W_out  = (const float*)d_in[15];
    const float* b_out  = (const float*)d_in[16];
    float* out = (float*)d_out;

    int Nc   = in_sizes[0] / 64;
    int Ncol = in_sizes[1] / 128;
    int E0   = in_sizes[2] / 2;
    int N    = Nc + Ncol;

    float *x0, *h1, *o1, *h2, *o2;
    float *pas1, *pad1, *pm1, *pdn1, *pas2, *pad2, *pm2, *pdn2, *e1, *e2, *wnf, *wcf;
    int *eidx;
    cudaGetSymbolAddress((void**)&x0,  g_x0);
    cudaGetSymbolAddress((void**)&h1,  g_h1);
    cudaGetSymbolAddress((void**)&o1,  g_o1);
    cudaGetSymbolAddress((void**)&h2,  g_h2);
    cudaGetSymbolAddress((void**)&o2,  g_o2);
    cudaGetSymbolAddress((void**)&pas1, g_as1);
    cudaGetSymbolAddress((void**)&pad1, g_ad1);
    cudaGetSymbolAddress((void**)&pm1,  g_m1);
    cudaGetSymbolAddress((void**)&pdn1, g_dn1);
    cudaGetSymbolAddress((void**)&pas2, g_as2);
    cudaGetSymbolAddress((void**)&pad2, g_ad2);
    cudaGetSymbolAddress((void**)&pm2,  g_m2);
    cudaGetSymbolAddress((void**)&pdn2, g_dn2);
    cudaGetSymbolAddress((void**)&e1,  g_e1);
    cudaGetSymbolAddress((void**)&e2,  g_e2);
    cudaGetSymbolAddress((void**)&wnf, g_wnf);
    cudaGetSymbolAddress((void**)&wcf, g_wcf);
    cudaGetSymbolAddress((void**)&eidx, g_eidx);

    // --- edge normalization ---
    detect_edges_kernel<<<1, 32>>>(edges, E0, N);
    convert_edges_kernel<<<(2 * E0 + 255) / 256, 256>>>(edges, 2 * E0);
    const int* er0 = eidx;
    const int* er1 = eidx + E0;

    // --- encoder (tile fold + GEMM + bias + relu) ---
    fold_w_kernel<<<(HID * 128 + 255) / 256, 256>>>(W_node, W_col);
    gemm_tf32_kernel<<<dim3(HID / 128, (Nc + 127) / 128), 256>>>(cs, wnf, x0, Nc, HID, 64, b_node, 1);
    gemm_tf32_kernel<<<dim3(HID / 128, (Ncol + 127) / 128), 256>>>(cols, wcf, x0 + (size_t)Nc * HID, Ncol, HID, 128, b_col, 1);

    // --- conv1 (8 heads) ---
    gemm_tf32_kernel<<<dim3(NH1 * HID / 128, (N + 127) / 128), 256>>>(x0, W1, h1, N, NH1 * HID, HID, nullptr, 0);
    att_coef_kernel<<<N, 32 * NH1>>>(h1, attS1, attD1, pas1, pad1, NH1);
    init_softmax_kernel<<<(N * NH1 + 255) / 256, 256>>>(pm1, pdn1, N * NH1);
    cudaMemsetAsync(o1, 0, (size_t)N * NH1 * HID * sizeof(float), 0);
    int tot1 = (E0 + N) * NH1;
    edge_logit_max_kernel<<<(tot1 + 255) / 256, 256>>>(pas1, pad1, er0, er1, E0, N, NH1, e1, pm1);
    edge_exp_kernel<<<(tot1 + 255) / 256, 256>>>(er1, E0, N, NH1, e1, pm1, pdn1);
    {
        long long threads = (long long)tot1 * 32;
        edge_aggregate_kernel<<<(unsigned)((threads + 255) / 256), 256>>>(h1, e1, pdn1, er0, er1, E0, N, NH1, o1);
    }
    bias_relu_kernel<<<((N * NH1 * HID / 4) + 255) / 256, 256>>>(o1, b1, N * NH1 * HID / 4, NH1 * HID);

    // --- conv2 (1 head, flipped edges) ---
    gemm_tf32_kernel<<<dim3(HID / 128, (N + 127) / 128), 256>>>(o1, W2, h2, N, HID, NH1 * HID, nullptr, 0);
    att_coef_kernel<<<N, 32>>>(h2, attS2, attD2, pas2, pad2, 1);
    init_softmax_kernel<<<(N + 255) / 256, 256>>>(pm2, pdn2, N);
    cudaMemsetAsync(o2, 0, (size_t)N * HID * sizeof(float), 0);
    int tot2 = E0 + N;
    edge_logit_max_kernel<<<(tot2 + 255) / 256, 256>>>(pas2, pad2, er1, er0, E0, N, 1, e2, pm2);
    edge_exp_kernel<<<(tot2 + 255) / 256, 256>>>(er0, E0, N, 1, e2, pm2, pdn2);
    {
        long long threads = (long long)tot2 * 32;
        edge_aggregate_kernel<<<(unsigned)((threads + 255) / 256), 256>>>(h2, e2, pdn2, er1, er0, E0, N, 1, o2);
    }
    bias_relu_kernel<<<((N * HID / 4) + 255) / 256, 256>>>(o2, b2, N * HID / 4, HID);

    // --- output projection (column nodes only) ---
    gemm_tf32_kernel<<<dim3(128 / 128, (Ncol + 127) / 128), 256>>>(o2 + (size_t)Nc * HID, W_out, out, Ncol, 128, HID, b_out, 0);
}

// round 5
// speedup vs baseline: 2.9521x; 2.4020x over previous
#include <cuda_runtime.h>
#include <float.h>
#include <stdint.h>

#define HID   256
#define NH1   8
#define MAXN  20992
#define MAXE0 102400
#define MAXT  (MAXE0 + MAXN)

// ---------------- static device scratch (no allocations allowed) ----------------
static __device__ float g_x0 [(size_t)MAXN * HID];
static __device__ float g_h1 [(size_t)MAXN * NH1 * HID];
static __device__ float g_o1 [(size_t)MAXN * NH1 * HID];
static __device__ float g_h2 [(size_t)MAXN * HID];
static __device__ float g_o2 [(size_t)MAXN * HID];
static __device__ float g_as1[MAXN * NH1];
static __device__ float g_ad1[MAXN * NH1];
static __device__ float g_m1 [MAXN * NH1];
static __device__ float g_dn1[MAXN * NH1];
static __device__ float g_as2[MAXN];
static __device__ float g_ad2[MAXN];
static __device__ float g_m2 [MAXN];
static __device__ float g_dn2[MAXN];
static __device__ float g_e1 [(size_t)MAXT * NH1];
static __device__ float g_e2 [MAXT];
static __device__ float g_wnf[HID * 64];
static __device__ float g_wcf[HID * 128];
static __device__ int   g_eidx[2 * MAXE0];
static __device__ int   g_is64;
// CSR (per direction)
static __device__ int g_deg1[MAXN];
static __device__ int g_deg2[MAXN];
static __device__ int g_rp1 [MAXN + 1];
static __device__ int g_rp2 [MAXN + 1];
static __device__ int g_pos1[MAXN];
static __device__ int g_pos2[MAXN];
static __device__ int g_el1 [MAXE0];
static __device__ int g_el2 [MAXE0];

// ---------------- edge dtype detection + normalization ----------------
__global__ void detect_edges_kernel(const void* p, int E0, int N) {
    if (blockIdx.x != 0 || threadIdx.x != 0) return;
    const long long* q = (const long long*)p;
    int scan = 2 * E0 < 512 ? 2 * E0 : 512;
    int ok = 1;
    for (int i = 0; i < scan; i++) {
        long long v = q[i];
        if (v < 0 || v >= (long long)N) { ok = 0; break; }
    }
    g_is64 = ok;
}

__global__ void convert_edges_kernel(const void* p, int n) {
    int i = blockIdx.x * blockDim.x + threadIdx.x;
    if (i >= n) return;
    if (g_is64) g_eidx[i] = (int)((const long long*)p)[i];
    else        g_eidx[i] = ((const int*)p)[i];
}

// ---------------- CSR construction ----------------
__global__ void count_deg_kernel(const int* __restrict__ er0, const int* __restrict__ er1,
                                 int E0, int* __restrict__ deg1, int* __restrict__ deg2) {
    int e = blockIdx.x * blockDim.x + threadIdx.x;
    if (e >= E0) return;
    atomicAdd(&deg1[er1[e]], 1);   // conv1 dst = edges[1]
    atomicAdd(&deg2[er0[e]], 1);   // conv2 dst = edges[0]
}

// single-block exclusive scan, 1024 threads, handles two arrays
__device__ void block_scan_one(const int* __restrict__ deg, int* __restrict__ rp,
                               int* __restrict__ pos, int N, int* warpsum, int* carry) {
    int tid = threadIdx.x, lane = tid & 31, wid = tid >> 5;
    if (tid == 0) *carry = 0;
    __syncthreads();
    for (int base = 0; base < N; base += 1024) {
        int i = base + tid;
        int v = (i < N) ? deg[i] : 0;
        int x = v;
#pragma unroll
        for (int o = 1; o < 32; o <<= 1) {
            int y = __shfl_up_sync(0xffffffffu, x, o);
            if (lane >= o) x += y;
        }
        if (lane == 31) warpsum[wid] = x;
        __syncthreads();
        if (wid == 0) {
            int s = warpsum[lane];
#pragma unroll
            for (int o = 1; o < 32; o <<= 1) {
                int y = __shfl_up_sync(0xffffffffu, s, o);
                if (lane >= o) s += y;
            }
            warpsum[lane] = s;
        }
        __syncthreads();
        int incl = x + (wid ? warpsum[wid - 1] : 0) + *carry;
        int excl = incl - v;
        if (i < N) { rp[i] = excl; pos[i] = excl; }
        __syncthreads();
        if (tid == 1023) *carry = incl;   // running total
        __syncthreads();
    }
    if (tid == 0) rp[N] = *carry;
}

__global__ void scan_kernel(const int* d1, int* rp1, int* ps1,
                            const int* d2, int* rp2, int* ps2, int N) {
    __shared__ int warpsum[32];
    __shared__ int carry;
    block_scan_one(d1, rp1, ps1, N, warpsum, &carry);
    __syncthreads();
    block_scan_one(d2, rp2, ps2, N, warpsum, &carry);
}

__global__ void fill_csr_kernel(const int* __restrict__ er0, const int* __restrict__ er1,
                                int E0, int* __restrict__ pos1, int* __restrict__ el1,
                                int* __restrict__ pos2, int* __restrict__ el2) {
    int e = blockIdx.x * blockDim.x + threadIdx.x;
    if (e >= E0) return;
    int p = atomicAdd(&pos1[er1[e]], 1); el1[p] = e;
    int q = atomicAdd(&pos2[er0[e]], 1); el2[q] = e;
}

// ---------------- weight folding for tile(x, (1,2)) ----------------
__global__ void fold_w_kernel(const float* __restrict__ Wn, const float* __restrict__ Wc) {
    int i = blockIdx.x * blockDim.x + threadIdx.x;
    if (i < HID * 64) {
        int j = i >> 6, k = i & 63;
        g_wnf[i] = Wn[j * 128 + k] + Wn[j * 128 + 64 + k];
    }
    if (i < HID * 128) {
        int j = i >> 7, k = i & 127;
        g_wcf[i] = Wc[j * 256 + k] + Wc[j * 256 + 128 + k];
    }
}

// ---------------- TF32 tensor-core GEMM ----------------
__device__ __forceinline__ float to_tf32(float x) {
    asm("cvt.rna.tf32.f32 %0, %0;" : "+f"(x));
    return x;
}

__device__ __forceinline__ void mma_tf32(float c[4],
                                         uint32_t a0, uint32_t a1, uint32_t a2, uint32_t a3,
                                         uint32_t b0, uint32_t b1) {
    asm volatile(
        "mma.sync.aligned.m16n8k8.row.col.f32.tf32.tf32.f32 "
        "{%0,%1,%2,%3}, {%4,%5,%6,%7}, {%8,%9}, {%0,%1,%2,%3};"
        : "+f"(c[0]), "+f"(c[1]), "+f"(c[2]), "+f"(c[3])
        : "r"(a0), "r"(a1), "r"(a2), "r"(a3), "r"(b0), "r"(b1));
}

#define SSTR 36

__global__ __launch_bounds__(256, 2) void gemm_tf32_kernel(
    const float* __restrict__ A, const float* __restrict__ B, float* __restrict__ C,
    int M, int N, int K, const float* __restrict__ bias, int relu)
{
    __shared__ float As[128 * SSTR];
    __shared__ float Bs[128 * SSTR];

    int tid  = threadIdx.x;
    int wid  = tid >> 5;
    int lane = tid & 31;
    int grp  = lane >> 2;
    int tig  = lane & 3;
    int wm   = wid & 1;
    int wn   = wid >> 1;
    int row0 = blockIdx.y * 128;
    int col0 = blockIdx.x * 128;

    int lrow = tid >> 3;
    int lkq  = (tid & 7) * 4;

    float c[4][4][4];
#pragma unroll
    for (int mi = 0; mi < 4; mi++)
#pragma unroll
        for (int ni = 0; ni < 4; ni++)
#pragma unroll
            for (int j = 0; j < 4; j++) c[mi][ni][j] = 0.f;

    for (int k0 = 0; k0 < K; k0 += 32) {
#pragma unroll
        for (int it = 0; it < 4; it++) {
            int r  = lrow + it * 32;
            int gr = row0 + r;
            float4 v = make_float4(0.f, 0.f, 0.f, 0.f);
            if (gr < M) v = *(const float4*)(A + (size_t)gr * K + k0 + lkq);
            float* s = As + r * SSTR + lkq;
            s[0] = to_tf32(v.x); s[1] = to_tf32(v.y);
            s[2] = to_tf32(v.z); s[3] = to_tf32(v.w);
        }
#pragma unroll
        for (int it = 0; it < 4; it++) {
            int r  = lrow + it * 32;
            float4 v = *(const float4*)(B + (size_t)(col0 + r) * K + k0 + lkq);
            float* s = Bs + r * SSTR + lkq;
            s[0] = to_tf32(v.x); s[1] = to_tf32(v.y);
            s[2] = to_tf32(v.z); s[3] = to_tf32(v.w);
        }
        __syncthreads();

#pragma unroll
        for (int ks = 0; ks < 4; ks++) {
            int kk = ks * 8;
            uint32_t af[4][4], bf[4][2];
#pragma unroll
            for (int mi = 0; mi < 4; mi++) {
                const float* ap = As + (wm * 64 + mi * 16 + grp) * SSTR + kk + tig;
                af[mi][0] = __float_as_uint(ap[0]);
                af[mi][1] = __float_as_uint(ap[8 * SSTR]);
                af[mi][2] = __float_as_uint(ap[4]);
                af[mi][3] = __float_as_uint(ap[8 * SSTR + 4]);
            }
#pragma unroll
            for (int ni = 0; ni < 4; ni++) {
                const float* bp = Bs + (wn * 32 + ni * 8 + grp) * SSTR + kk + tig;
                bf[ni][0] = __float_as_uint(bp[0]);
                bf[ni][1] = __float_as_uint(bp[4]);
            }
#pragma unroll
            for (int mi = 0; mi < 4; mi++)
#pragma unroll
                for (int ni = 0; ni < 4; ni++)
                    mma_tf32(c[mi][ni], af[mi][0], af[mi][1], af[mi][2], af[mi][3],
                             bf[ni][0], bf[ni][1]);
        }
        __syncthreads();
    }

#pragma unroll
    for (int mi = 0; mi < 4; mi++) {
#pragma unroll
        for (int half = 0; half < 2; half++) {
            int r = row0 + wm * 64 + mi * 16 + grp + half * 8;
            if (r >= M) continue;
#pragma unroll
            for (int ni = 0; ni < 4; ni++) {
                int cc = col0 + wn * 32 + ni * 8 + 2 * tig;
                float v0 = c[mi][ni][half * 2 + 0];
                float v1 = c[mi][ni][half * 2 + 1];
                if (bias) { v0 += bias[cc]; v1 += bias[cc + 1]; }
                if (relu) { v0 = v0 > 0.f ? v0 : 0.f; v1 = v1 > 0.f ? v1 : 0.f; }
                *(float2*)(C + (size_t)r * N + cc) = make_float2(v0, v1);
            }
        }
    }
}

// ---------------- attention coefficients: warp per (node, head) ----------------
__global__ void att_coef_kernel(const float* __restrict__ h,
                                const float* __restrict__ avs, const float* __restrict__ avd,
                                float* __restrict__ os, float* __restrict__ od, int H)
{
    int n = blockIdx.x;
    int w = threadIdx.x >> 5;
    int lane = threadIdx.x & 31;
    const float* hp = h + ((size_t)n * H + w) * HID;
    float s = 0.f, d = 0.f;
    for (int c = lane; c < HID; c += 32) {
        float v = hp[c];
        s += v * avs[w * HID + c];
        d += v * avd[w * HID + c];
    }
#pragma unroll
    for (int o = 16; o; o >>= 1) {
        s += __shfl_down_sync(0xffffffffu, s, o);
        d += __shfl_down_sync(0xffffffffu, d, o);
    }
    if (lane == 0) { os[n * H + w] = s; od[n * H + w] = d; }
}

__global__ void init_softmax_kernel(float* __restrict__ m, float* __restrict__ dn, int n) {
    int i = blockIdx.x * blockDim.x + threadIdx.x;
    if (i < n) { m[i] = -FLT_MAX; dn[i] = 0.f; }
}

__device__ __forceinline__ void atomicMaxF(float* addr, float v) {
    int old = __float_as_int(*addr);
    while (__int_as_float(old) < v) {
        int assumed = old;
        old = atomicCAS((int*)addr, assumed, __float_as_int(v));
        if (old == assumed) break;
    }
}

__global__ void edge_logit_max_kernel(const float* __restrict__ as_, const float* __restrict__ ad_,
                                      const int* __restrict__ esrc, const int* __restrict__ edst,
                                      int E0, int N, int H,
                                      float* __restrict__ ebuf, float* __restrict__ m)
{
    int idx = blockIdx.x * blockDim.x + threadIdx.x;
    int total = (E0 + N) * H;
    if (idx >= total) return;
    int i = idx / H, hh = idx - i * H;
    int src, dst;
    if (i < E0) { src = esrc[i]; dst = edst[i]; }
    else        { src = dst = i - E0; }
    float e = as_[src * H + hh] + ad_[dst * H + hh];
    e = e > 0.f ? e : 0.2f * e;
    ebuf[idx] = e;
    atomicMaxF(&m[dst * H + hh], e);
}

__global__ void edge_exp_kernel(const int* __restrict__ edst, int E0, int N, int H,
                                float* __restrict__ ebuf,
                                const float* __restrict__ m, float* __restrict__ dn)
{
    int idx = blockIdx.x * blockDim.x + threadIdx.x;
    int total = (E0 + N) * H;
    if (idx >= total) return;
    int i = idx / H, hh = idx - i * H;
    int dst = (i < E0) ? edst[i] : (i - E0);
    float v = expf(ebuf[idx] - m[dst * H + hh]);
    ebuf[idx] = v;
    atomicAdd(&dn[dst * H + hh], v);
}

// ---------------- gather aggregation: warp per (dst, head), no atomics ----------
// out[n,h,:] = relu( bias[h,:] + sum_{e in CSR(n)} alpha_e * h[src_e,h,:] + alpha_self*h[n,h,:] )
__global__ __launch_bounds__(256) void gather_aggregate_kernel(
    const float* __restrict__ h, const float* __restrict__ ebuf,
    const float* __restrict__ dn, const int* __restrict__ esrc,
    const int* __restrict__ rp, const int* __restrict__ el,
    int E0, int N, int H, const float* __restrict__ bias, int relu,
    float* __restrict__ out)
{
    int w    = (blockIdx.x * blockDim.x + threadIdx.x) >> 5;
    int lane = threadIdx.x & 31;
    if (w >= N * H) return;
    int n  = w / H;
    int hh = w - n * H;

    float inv = 1.f / (dn[w] + 1e-16f);

    // self-loop term
    float a_self = ebuf[(size_t)(E0 + n) * H + hh] * inv;
    const float4* hp = (const float4*)(h + (size_t)w * HID);
    float4 u0 = hp[lane], u1 = hp[lane + 32];
    float4 acc0 = make_float4(a_self * u0.x, a_self * u0.y, a_self * u0.z, a_self * u0.w);
    float4 acc1 = make_float4(a_self * u1.x, a_self * u1.y, a_self * u1.z, a_self * u1.w);

    int jb = rp[n], je = rp[n + 1];
    for (int j = jb; j < je; j++) {
        int e   = el[j];            // broadcast load
        int src = esrc[e];
        float al = ebuf[(size_t)e * H + hh] * inv;
        const float4* sp = (const float4*)(h + ((size_t)src * H + hh) * HID);
        float4 v0 = sp[lane], v1 = sp[lane + 32];
        acc0.x += al * v0.x; acc0.y += al * v0.y; acc0.z += al * v0.z; acc0.w += al * v0.w;
        acc1.x += al * v1.x; acc1.y += al * v1.y; acc1.z += al * v1.z; acc1.w += al * v1.w;
    }

    const float4* bp = (const float4*)(bias + (size_t)hh * HID);
    float4 b0 = bp[lane], b1 = bp[lane + 32];
    acc0.x += b0.x; acc0.y += b0.y; acc0.z += b0.z; acc0.w += b0.w;
    acc1.x += b1.x; acc1.y += b1.y; acc1.z += b1.z; acc1.w += b1.w;
    if (relu) {
        acc0.x = acc0.x > 0.f ? acc0.x : 0.f;  acc0.y = acc0.y > 0.f ? acc0.y : 0.f;
        acc0.z = acc0.z > 0.f ? acc0.z : 0.f;  acc0.w = acc0.w > 0.f ? acc0.w : 0.f;
        acc1.x = acc1.x > 0.f ? acc1.x : 0.f;  acc1.y = acc1.y > 0.f ? acc1.y : 0.f;
        acc1.z = acc1.z > 0.f ? acc1.z : 0.f;  acc1.w = acc1.w > 0.f ? acc1.w : 0.f;
    }
    float4* op = (float4*)(out + (size_t)w * HID);
    op[lane]      = acc0;
    op[lane + 32] = acc1;
}

// ---------------- launch ----------------
extern "C" void kernel_launch(void* const* d_in, const int* in_sizes, int n_in,
                              void* d_out, int out_size)
{
    const float* cs    = (const float*)d_in[0];
    const float* cols  = (const float*)d_in[1];
    const void*  edges = d_in[2];
    const float* W_node = (const float*)d_in[3];
    const float* b_node = (const float*)d_in[4];
    const float* W_col  = (const float*)d_in[5];
    const float* b_col  = (const float*)d_in[6];
    const float* W1     = (const float*)d_in[7];
    const float* attS1  = (const float*)d_in[8];
    const float* attD1  = (const float*)d_in[9];
    const float* b1     = (const float*)d_in[10];
    const float* W2     = (const float*)d_in[11];
    const float* attS2  = (const float*)d_in[12];
    const float* attD2  = (const float*)d_in[13];
    const float* b2     = (const float*)d_in[14];
    const float* W_out  = (const float*)d_in[15];
    const float* b_out  = (const float*)d_in[16];
    float* out = (float*)d_out;

    int Nc   = in_sizes[0] / 64;
    int Ncol = in_sizes[1] / 128;
    int E0   = in_sizes[2] / 2;
    int N    = Nc + Ncol;

    float *x0, *h1, *o1, *h2, *o2;
    float *pas1, *pad1, *pm1, *pdn1, *pas2, *pad2, *pm2, *pdn2, *e1, *e2, *wnf, *wcf;
    int *eidx, *deg1, *deg2, *rp1, *rp2, *pos1, *pos2, *el1, *el2;
    cudaGetSymbolAddress((void**)&x0,  g_x0);
    cudaGetSymbolAddress((void**)&h1,  g_h1);
    cudaGetSymbolAddress((void**)&o1,  g_o1);
    cudaGetSymbolAddress((void**)&h2,  g_h2);
    cudaGetSymbolAddress((void**)&o2,  g_o2);
    cudaGetSymbolAddress((void**)&pas1, g_as1);
    cudaGetSymbolAddress((void**)&pad1, g_ad1);
    cudaGetSymbolAddress((void**)&pm1,  g_m1);
    cudaGetSymbolAddress((void**)&pdn1, g_dn1);
    cudaGetSymbolAddress((void**)&pas2, g_as2);
    cudaGetSymbolAddress((void**)&pad2, g_ad2);
    cudaGetSymbolAddress((void**)&pm2,  g_m2);
    cudaGetSymbolAddress((void**)&pdn2, g_dn2);
    cudaGetSymbolAddress((void**)&e1,  g_e1);
    cudaGetSymbolAddress((void**)&e2,  g_e2);
    cudaGetSymbolAddress((void**)&wnf, g_wnf);
    cudaGetSymbolAddress((void**)&wcf, g_wcf);
    cudaGetSymbolAddress((void**)&eidx, g_eidx);
    cudaGetSymbolAddress((void**)&deg1, g_deg1);
    cudaGetSymbolAddress((void**)&deg2, g_deg2);
    cudaGetSymbolAddress((void**)&rp1,  g_rp1);
    cudaGetSymbolAddress((void**)&rp2,  g_rp2);
    cudaGetSymbolAddress((void**)&pos1, g_pos1);
    cudaGetSymbolAddress((void**)&pos2, g_pos2);
    cudaGetSymbolAddress((void**)&el1,  g_el1);
    cudaGetSymbolAddress((void**)&el2,  g_el2);

    // --- edge normalization + CSR build ---
    detect_edges_kernel<<<1, 32>>>(edges, E0, N);
    convert_edges_kernel<<<(2 * E0 + 255) / 256, 256>>>(edges, 2 * E0);
    const int* er0 = eidx;
    const int* er1 = eidx + E0;
    cudaMemsetAsync(deg1, 0, N * sizeof(int), 0);
    cudaMemsetAsync(deg2, 0, N * sizeof(int), 0);
    count_deg_kernel<<<(E0 + 255) / 256, 256>>>(er0, er1, E0, deg1, deg2);
    scan_kernel<<<1, 1024>>>(deg1, rp1, pos1, deg2, rp2, pos2, N);
    fill_csr_kernel<<<(E0 + 255) / 256, 256>>>(er0, er1, E0, pos1, el1, pos2, el2);

    // --- encoder (tile fold + GEMM + bias + relu) ---
    fold_w_kernel<<<(HID * 128 + 255) / 256, 256>>>(W_node, W_col);
    gemm_tf32_kernel<<<dim3(HID / 128, (Nc + 127) / 128), 256>>>(cs, wnf, x0, Nc, HID, 64, b_node, 1);
    gemm_tf32_kernel<<<dim3(HID / 128, (Ncol + 127) / 128), 256>>>(cols, wcf, x0 + (size_t)Nc * HID, Ncol, HID, 128, b_col, 1);

    // --- conv1 (8 heads) ---
    gemm_tf32_kernel<<<dim3(NH1 * HID / 128, (N + 127) / 128), 256>>>(x0, W1, h1, N, NH1 * HID, HID, nullptr, 0);
    att_coef_kernel<<<N, 32 * NH1>>>(h1, attS1, attD1, pas1, pad1, NH1);
    init_softmax_kernel<<<(N * NH1 + 255) / 256, 256>>>(pm1, pdn1, N * NH1);
    int tot1 = (E0 + N) * NH1;
    edge_logit_max_kernel<<<(tot1 + 255) / 256, 256>>>(pas1, pad1, er0, er1, E0, N, NH1, e1, pm1);
    edge_exp_kernel<<<(tot1 + 255) / 256, 256>>>(er1, E0, N, NH1, e1, pm1, pdn1);
    {
        long long threads = (long long)N * NH1 * 32;
        gather_aggregate_kernel<<<(unsigned)((threads + 255) / 256), 256>>>(
            h1, e1, pdn1, er0, rp1, el1, E0, N, NH1, b1, 1, o1);
    }

    // --- conv2 (1 head, flipped edges) ---
    gemm_tf32_kernel<<<dim3(HID / 128, (N + 127) / 128), 256>>>(o1, W2, h2, N, HID, NH1 * HID, nullptr, 0);
    att_coef_kernel<<<N, 32>>>(h2, attS2, attD2, pas2, pad2, 1);
    init_softmax_kernel<<<(N + 255) / 256, 256>>>(pm2, pdn2, N);
    int tot2 = E0 + N;
    edge_logit_max_kernel<<<(tot2 + 255) / 256, 256>>>(pas2, pad2, er1, er0, E0, N, 1, e2, pm2);
    edge_exp_kernel<<<(tot2 + 255) / 256, 256>>>(er0, E0, N, 1, e2, pm2, pdn2);
    {
        long long threads = (long long)N * 32;
        gather_aggregate_kernel<<<(unsigned)((threads + 255) / 256), 256>>>(
            h2, e2, pdn2, er1, rp2, el2, E0, N, 1, b2, 1, o2);
    }

    // --- output projection (column nodes only) ---
    gemm_tf32_kernel<<<dim3(128 / 128, (Ncol + 127) / 128), 256>>>(o2 + (size_t)Nc * HID, W_out, out, Ncol, 128, HID, b_out, 0);
}